// round 12
// baseline (speedup 1.0000x reference)
#include <cuda_runtime.h>
#include <math.h>
#include <stdint.h>

#define BB 4
#define C 96
#define H 128
#define W 128
#define HW (H*W)          // 16384
#define KKc 9
#define CK (C*KKc)        // 864
#define NPIX (BB*HW)      // 65536 per channel

typedef unsigned long long ull;

// ---------------- device scratch (no allocations allowed) ----------------
__device__ float  g_col [ (size_t)BB * CK * HW ];   // 226.5 MB deform-col
__device__ ull    g_wtp [ CK * 14 ];                // offset|mask weights, opair-packed
__device__ float4 g_wts [ (size_t)BB * KKc * HW ];  // separable bilinear weights
__device__ int    g_idxn[ (size_t)BB * KKc * HW ];  // gather base index
__device__ float  g_conv[ (size_t)BB * C * HW ];    // deform-conv output
__device__ float  g_act [ (size_t)BB * C * HW ];    // post BN+leakyrelu
__device__ float  g_sums[ 2 * C ];                  // atomic sum | sumsq

// packed f32x2 FMA (FFMA2)
#define FMA2(d, a, b) \
    asm("fma.rn.f32x2 %0, %1, %2, %0;" : "+l"(d) : "l"(a), "l"(b))

__device__ __forceinline__ ull bcast2(float v) {
    ull r; unsigned u = __float_as_uint(v);
    asm("mov.b64 %0, {%1, %1};" : "=l"(r) : "r"(u));
    return r;
}

// ---------------- weight prep (+ zero BN sums, folded) ----------------
__global__ void wprep_kernel(const float* __restrict__ offw,
                             const float* __restrict__ modw,
                             ull* __restrict__ wtp,
                             float* __restrict__ sums) {
    int t = blockIdx.x * blockDim.x + threadIdx.x;
    if (blockIdx.x == 0 && threadIdx.x < 2 * C) sums[threadIdx.x] = 0.f;
    if (t >= CK * 14) return;
    int ck = t / 14, j = t - ck * 14;
    int o0 = 2 * j, o1 = 2 * j + 1;
    float a = (o0 < 18) ? offw[o0 * CK + ck] : modw[(o0 - 18) * CK + ck];
    float b = 0.f;
    if (o1 < 27)
        b = (o1 < 18) ? offw[o1 * CK + ck] : modw[(o1 - 18) * CK + ck];
    float2 p = make_float2(a, b);
    wtp[t] = *reinterpret_cast<ull*>(&p);
}

// ---------------------------------------------------------------------------
// Direct 3x3 conv producing 27 outputs/pixel + separable bilinear tables.
// 512 threads = 8 channel-groups (12 ch each) x 64 pixel-columns x 2 rows.
// ---------------------------------------------------------------------------
#define OFF_SMEM (7 * 64 * 28 * 8)   // 100352 B

__global__ void __launch_bounds__(512) offconv_kernel(
    const ull* __restrict__ wtp, const float* __restrict__ X,
    const float* __restrict__ off_b, const float* __restrict__ mod_b,
    float4* __restrict__ wts, int* __restrict__ idxn)
{
    extern __shared__ ull red[];     // [7][64][28]

    int tid  = threadIdx.x;
    int lane = tid & 63;
    int grp  = tid >> 6;             // 0..7
    int half = blockIdx.x & 1;
    int h0   = (blockIdx.x >> 1) * 2;
    int b    = blockIdx.y;
    int pix  = half * 64 + lane;

    const float* Xb = X + (size_t)b * C * HW;

    ull acc[2][14];
    #pragma unroll
    for (int r = 0; r < 2; r++)
        #pragma unroll
        for (int j = 0; j < 14; j++) acc[r][j] = 0ull;

    bool xm_ok = (pix > 0), xp_ok = (pix < W - 1);
    int c0 = grp * 12;
    for (int ci = 0; ci < 12; ci++) {
        int c = c0 + ci;
        ull tb[4][3];
        #pragma unroll
        for (int rr = 0; rr < 4; rr++) {
            int y = h0 - 1 + rr;
            bool yok = (y >= 0) && (y < H);
            const float* row = Xb + (size_t)c * HW + y * W + pix;
            tb[rr][0] = bcast2((yok && xm_ok) ? row[-1] : 0.f);
            tb[rr][1] = bcast2(yok ? row[0] : 0.f);
            tb[rr][2] = bcast2((yok && xp_ok) ? row[1] : 0.f);
        }
        const ulonglong2* wrow =
            reinterpret_cast<const ulonglong2*>(wtp + (size_t)c * 9 * 14);
        #pragma unroll
        for (int ky = 0; ky < 3; ky++)
            #pragma unroll
            for (int kx = 0; kx < 3; kx++) {
                int tap = ky * 3 + kx;
                ull t0 = tb[ky][kx], t1 = tb[ky + 1][kx];
                #pragma unroll
                for (int j2 = 0; j2 < 7; j2++) {
                    ulonglong2 wv = wrow[tap * 7 + j2];
                    FMA2(acc[0][2 * j2],     wv.x, t0);
                    FMA2(acc[1][2 * j2],     wv.x, t1);
                    FMA2(acc[0][2 * j2 + 1], wv.y, t0);
                    FMA2(acc[1][2 * j2 + 1], wv.y, t1);
                }
            }
    }

    if (grp > 0) {
        ull* dst = red + ((size_t)(grp - 1) * 64 + lane) * 28;
        #pragma unroll
        for (int r = 0; r < 2; r++)
            #pragma unroll
            for (int j = 0; j < 14; j++)
                dst[r * 14 + j] = acc[r][j];
    }
    __syncthreads();
    if (grp != 0) return;

    #pragma unroll
    for (int g = 0; g < 7; g++) {
        const ull* src = red + ((size_t)g * 64 + lane) * 28;
        #pragma unroll
        for (int r = 0; r < 2; r++)
            #pragma unroll
            for (int j = 0; j < 14; j++) {
                ull p = src[r * 14 + j];
                float2 pa = *reinterpret_cast<float2*>(&acc[r][j]);
                float2 pb = *reinterpret_cast<float2*>(&p);
                pa.x += pb.x; pa.y += pb.y;
                acc[r][j] = *reinterpret_cast<ull*>(&pa);
            }
    }

    #pragma unroll
    for (int r = 0; r < 2; r++) {
        int h = h0 + r;
        #pragma unroll
        for (int kk = 0; kk < KKc; kk++) {
            float2 oyx = *reinterpret_cast<float2*>(&acc[r][kk]);
            float2 mp  = *reinterpret_cast<float2*>(&acc[r][9 + (kk >> 1)]);
            float mraw = (kk & 1) ? mp.y : mp.x;
            float offy = oyx.x + off_b[2 * kk];
            float offx = oyx.y + off_b[2 * kk + 1];
            float mval = 2.f / (1.f + expf(-(mraw + mod_b[kk])));

            float py = (float)h   - 1.f + (float)(kk / 3) + offy;
            float px = (float)pix - 1.f + (float)(kk % 3) + offx;
            float y0f = floorf(py), x0f = floorf(px);
            float dy = py - y0f, dx = px - x0f;
            int y0 = (int)y0f, x0 = (int)x0f;
            int y1 = y0 + 1,   x1 = x0 + 1;

            bool vx0 = (x0 >= 0) && (x0 < W);
            bool vx1 = (x1 >= 0) && (x1 < W);
            int x0c = min(max(x0, 0), W - 1), x1c = min(max(x1, 0), W - 1);
            int bx  = min(max(x0, 0), W - 2);
            float wxl = ((bx == x0c && vx0) ? (1.f - dx) : 0.f)
                      + ((bx == x1c && vx1) ? dx : 0.f);
            float wxr = ((bx + 1 == x0c && vx0) ? (1.f - dx) : 0.f)
                      + ((bx + 1 == x1c && vx1) ? dx : 0.f);

            bool vy0 = (y0 >= 0) && (y0 < H);
            bool vy1 = (y1 >= 0) && (y1 < H);
            int y0c = min(max(y0, 0), H - 1), y1c = min(max(y1, 0), H - 1);
            int by  = min(max(y0, 0), H - 2);
            float wyt = (((by == y0c && vy0) ? (1.f - dy) : 0.f)
                       + ((by == y1c && vy1) ? dy : 0.f)) * mval;
            float wyb = (((by + 1 == y0c && vy0) ? (1.f - dy) : 0.f)
                       + ((by + 1 == y1c && vy1) ? dy : 0.f)) * mval;

            size_t t = (((size_t)b * KKc + kk) << 14) + h * W + pix;
            wts[t]  = make_float4(wxl, wxr, wyt, wyb);
            idxn[t] = by * W + bx;
        }
    }
}

// ---------------- deformable im2col via precomputed tables ----------------
__global__ void deform_col_kernel(const float* __restrict__ in,
                                  const float4* __restrict__ wts,
                                  const int* __restrict__ idxn,
                                  float* __restrict__ col) {
    int t = blockIdx.x * blockDim.x + threadIdx.x;
    if (t >= BB * KKc * HW) return;
    int hw = t & (HW - 1);
    int u  = t >> 14;
    int kk = u % KKc;
    int b  = u / KKc;

    float4 w = wts[t];
    int base = idxn[t];

    const float* p = in + (size_t)b * C * HW;
    float* o = col + ((size_t)b * CK + kk) * HW + hw;
    #pragma unroll 4
    for (int c = 0; c < C; c++) {
        float top = p[base] * w.x + p[base + 1] * w.y;
        float bot = p[base + W] * w.x + p[base + W + 1] * w.y;
        *o = top * w.z + bot * w.w;
        p += HW;
        o += (size_t)KKc * HW;
    }
}

// ---------------- main GEMM: double-buffered smem, single sync/chunk -------
// dyn smem: As0[32][98] As1[32][98] Bs0[32][128] Bs1[32][128] = 57856 B
#define GEMM_SMEM 57856

__global__ void __launch_bounds__(256, 2) sgemm96_kernel(
    const float* __restrict__ A,      // [96][864]
    const float* __restrict__ Bmat,   // [B][864][HW]
    float* __restrict__ Out,          // [B][96][HW]
    float* __restrict__ sums)         // [2][96] atomic accumulators
{
    constexpr int BK = 32, BN = 128, BM = 96;
    constexpr int NCHUNK = CK / BK;    // 27
    extern __shared__ float dsm[];
    float (*AsA)[BM + 2] = (float(*)[BM + 2])dsm;              // 3136 f
    float (*AsB)[BM + 2] = (float(*)[BM + 2])(dsm + 3136);     // 3136 f
    float (*BsA)[BN]     = (float(*)[BN])(dsm + 6272);         // 4096 f
    float (*BsB)[BN]     = (float(*)[BN])(dsm + 10368);        // 4096 f

    int tid = threadIdx.x;
    int b   = blockIdx.y;
    int n0  = blockIdx.x * BN;
    int tx  = tid & 15;
    int ty  = tid >> 4;

    const float* Bb = Bmat + (size_t)b * CK * HW;

    ull acc2[6][4];
    #pragma unroll
    for (int i = 0; i < 6; i++)
        #pragma unroll
        for (int j = 0; j < 4; j++) acc2[i][j] = 0ull;

    int br = tid >> 3;           // 0..31  (B row)
    int bq = tid & 7;            // 0..7   (col group)

    float4 ra[3], rb[4];

    auto gload = [&](int k0) {
        #pragma unroll
        for (int i = 0; i < 3; i++) {
            int e = tid + i * 256;
            int m = e >> 3, kq = e & 7;
            ra[i] = *reinterpret_cast<const float4*>(&A[m * CK + k0 + kq * 4]);
        }
        #pragma unroll
        for (int j = 0; j < 4; j++)
            rb[j] = *reinterpret_cast<const float4*>(
                Bb + (size_t)(k0 + br) * HW + n0 + bq * 4 + j * 32);
    };
    auto sstore = [&](float (*As)[BM + 2], float (*Bs)[BN]) {
        #pragma unroll
        for (int i = 0; i < 3; i++) {
            int e = tid + i * 256;
            int m = e >> 3, kq = e & 7;
            As[kq * 4 + 0][m] = ra[i].x;
            As[kq * 4 + 1][m] = ra[i].y;
            As[kq * 4 + 2][m] = ra[i].z;
            As[kq * 4 + 3][m] = ra[i].w;
        }
        #pragma unroll
        for (int j = 0; j < 4; j++)
            *reinterpret_cast<float4*>(&Bs[br][bq * 4 + j * 32]) = rb[j];
    };

    gload(0);
    sstore(AsA, BsA);
    __syncthreads();

    for (int ch = 0; ch < NCHUNK; ch++) {
        bool more = (ch + 1 < NCHUNK);
        if (more) gload((ch + 1) * BK);           // prefetch overlaps compute

        float (*As)[BM + 2] = (ch & 1) ? AsB : AsA;
        float (*Bs)[BN]     = (ch & 1) ? BsB : BsA;

        #pragma unroll
        for (int k = 0; k < BK; k++) {
            float2 a01 = *reinterpret_cast<const float2*>(&As[k][ty * 6]);
            float2 a23 = *reinterpret_cast<const float2*>(&As[k][ty * 6 + 2]);
            float2 a45 = *reinterpret_cast<const float2*>(&As[k][ty * 6 + 4]);
            ull a2[6];
            a2[0] = bcast2(a01.x); a2[1] = bcast2(a01.y);
            a2[2] = bcast2(a23.x); a2[3] = bcast2(a23.y);
            a2[4] = bcast2(a45.x); a2[5] = bcast2(a45.y);

            float4 bl = *reinterpret_cast<const float4*>(&Bs[k][tx * 4]);
            float4 bh = *reinterpret_cast<const float4*>(&Bs[k][64 + tx * 4]);
            float2 q0 = make_float2(bl.x, bl.y);
            float2 q1 = make_float2(bl.z, bl.w);
            float2 q2 = make_float2(bh.x, bh.y);
            float2 q3 = make_float2(bh.z, bh.w);
            ull b0 = *reinterpret_cast<ull*>(&q0);
            ull b1 = *reinterpret_cast<ull*>(&q1);
            ull b2v = *reinterpret_cast<ull*>(&q2);
            ull b3 = *reinterpret_cast<ull*>(&q3);

            #pragma unroll
            for (int i = 0; i < 6; i++) {
                FMA2(acc2[i][0], a2[i], b0);
                FMA2(acc2[i][1], a2[i], b1);
                FMA2(acc2[i][2], a2[i], b2v);
                FMA2(acc2[i][3], a2[i], b3);
            }
        }
        if (more)
            sstore((ch & 1) ? AsA : AsB, (ch & 1) ? BsA : BsB);
        __syncthreads();
    }

    #pragma unroll
    for (int i = 0; i < 6; i++) {
        int m = ty * 6 + i;
        float* op = Out + ((size_t)b * BM + m) * HW + n0 + tx * 4;
        float2 p0 = *reinterpret_cast<float2*>(&acc2[i][0]);
        float2 p1 = *reinterpret_cast<float2*>(&acc2[i][1]);
        float2 p2 = *reinterpret_cast<float2*>(&acc2[i][2]);
        float2 p3 = *reinterpret_cast<float2*>(&acc2[i][3]);
        *reinterpret_cast<float4*>(op)      = make_float4(p0.x, p0.y, p1.x, p1.y);
        *reinterpret_cast<float4*>(op + 64) = make_float4(p2.x, p2.y, p3.x, p3.y);

        float s = p0.x + p0.y + p1.x + p1.y + p2.x + p2.y + p3.x + p3.y;
        float q = p0.x * p0.x + p0.y * p0.y + p1.x * p1.x + p1.y * p1.y
                + p2.x * p2.x + p2.y * p2.y + p3.x * p3.x + p3.y * p3.y;
        #pragma unroll
        for (int off = 8; off > 0; off >>= 1) {
            s += __shfl_down_sync(0xffffffffu, s, off, 16);
            q += __shfl_down_sync(0xffffffffu, q, off, 16);
        }
        if (tx == 0) {
            atomicAdd(&sums[m], s);
            atomicAdd(&sums[C + m], q);
        }
    }
}

// ---------------- batch norm apply (stats finalized in-block) --------------
__global__ void bn_lrelu_kernel(const float* __restrict__ X,
                                const float* __restrict__ gam,
                                const float* __restrict__ bet,
                                const float* __restrict__ sums,
                                float* __restrict__ O) {
    __shared__ float sc, sh;
    int idx = blockIdx.x * blockDim.x + threadIdx.x;
    int c = (idx / HW) % C;          // constant per block (256 | HW)
    if (threadIdx.x == 0) {
        float inv = 1.f / (float)NPIX;
        float mean = sums[c] * inv;
        float var  = sums[C + c] * inv - mean * mean;
        float rstd = rsqrtf(var + 1e-5f);
        sc = rstd * gam[c];
        sh = bet[c] - mean * rstd * gam[c];
    }
    __syncthreads();
    float v = X[idx] * sc + sh;
    O[idx] = v >= 0.f ? v : 0.1f * v;
}

__global__ void bn_add_kernel(const float* __restrict__ Xres,
                              const float* __restrict__ Hc,
                              const float* __restrict__ gam,
                              const float* __restrict__ bet,
                              const float* __restrict__ sums,
                              float* __restrict__ O) {
    __shared__ float sc, sh;
    int idx = blockIdx.x * blockDim.x + threadIdx.x;
    int c = (idx / HW) % C;
    if (threadIdx.x == 0) {
        float inv = 1.f / (float)NPIX;
        float mean = sums[c] * inv;
        float var  = sums[C + c] * inv - mean * mean;
        float rstd = rsqrtf(var + 1e-5f);
        sc = rstd * gam[c];
        sh = bet[c] - mean * rstd * gam[c];
    }
    __syncthreads();
    O[idx] = Xres[idx] + Hc[idx] * sc + sh;
}

// ---------------- launch ----------------
extern "C" void kernel_launch(void* const* d_in, const int* in_sizes, int n_in,
                              void* d_out, int out_size) {
    const float* x        = (const float*)d_in[0];
    const float* d1_off_w = (const float*)d_in[1];
    const float* d1_off_b = (const float*)d_in[2];
    const float* d1_mod_w = (const float*)d_in[3];
    const float* d1_mod_b = (const float*)d_in[4];
    const float* d1_w     = (const float*)d_in[5];
    const float* d2_off_w = (const float*)d_in[6];
    const float* d2_off_b = (const float*)d_in[7];
    const float* d2_mod_w = (const float*)d_in[8];
    const float* d2_mod_b = (const float*)d_in[9];
    const float* d2_w     = (const float*)d_in[10];
    const float* bn_g     = (const float*)d_in[11];
    const float* bn_b     = (const float*)d_in[12];
    float* out = (float*)d_out;

    float *p_col, *p_conv, *p_act, *p_sums;
    ull* p_wtp; float4* p_wts; int* p_idxn;
    cudaGetSymbolAddress((void**)&p_col,   g_col);
    cudaGetSymbolAddress((void**)&p_wtp,   g_wtp);
    cudaGetSymbolAddress((void**)&p_wts,   g_wts);
    cudaGetSymbolAddress((void**)&p_idxn,  g_idxn);
    cudaGetSymbolAddress((void**)&p_conv,  g_conv);
    cudaGetSymbolAddress((void**)&p_act,   g_act);
    cudaGetSymbolAddress((void**)&p_sums,  g_sums);

    cudaFuncSetAttribute(offconv_kernel,
                         cudaFuncAttributeMaxDynamicSharedMemorySize, OFF_SMEM);
    cudaFuncSetAttribute(sgemm96_kernel,
                         cudaFuncAttributeMaxDynamicSharedMemorySize, GEMM_SMEM);

    const int NT = 256;
    const int nCol  = BB * KKc * HW;                 // 589824
    const int nElem = BB * C * HW;                   // 6291456
    dim3 gemm_grid(HW / 128, BB);                    // (128, 4)
    dim3 off_grid(H, BB);                            // (128, 4)

    // ---------- layer 1 ----------
    wprep_kernel<<<(CK * 14 + NT - 1) / NT, NT>>>(d1_off_w, d1_mod_w, p_wtp, p_sums);
    offconv_kernel<<<off_grid, 512, OFF_SMEM>>>(p_wtp, x, d1_off_b, d1_mod_b, p_wts, p_idxn);
    deform_col_kernel<<<(nCol + NT - 1) / NT, NT>>>(x, p_wts, p_idxn, p_col);
    sgemm96_kernel<<<gemm_grid, NT, GEMM_SMEM>>>(d1_w, p_col, p_conv, p_sums);
    bn_lrelu_kernel<<<nElem / NT, NT>>>(p_conv, bn_g, bn_b, p_sums, p_act);

    // ---------- layer 2 ----------
    wprep_kernel<<<(CK * 14 + NT - 1) / NT, NT>>>(d2_off_w, d2_mod_w, p_wtp, p_sums);
    offconv_kernel<<<off_grid, 512, OFF_SMEM>>>(p_wtp, p_act, d2_off_b, d2_mod_b, p_wts, p_idxn);
    deform_col_kernel<<<(nCol + NT - 1) / NT, NT>>>(p_act, p_wts, p_idxn, p_col);
    sgemm96_kernel<<<gemm_grid, NT, GEMM_SMEM>>>(d2_w, p_col, p_conv, p_sums);
    bn_add_kernel<<<nElem / NT, NT>>>(x, p_conv, bn_g, bn_b, p_sums, out);
}

// round 14
// speedup vs baseline: 1.0200x; 1.0200x over previous
#include <cuda_runtime.h>
#include <math.h>
#include <stdint.h>

#define BB 4
#define C 96
#define H 128
#define W 128
#define HW (H*W)          // 16384
#define KKc 9
#define CK (C*KKc)        // 864
#define NPIX (BB*HW)      // 65536 per channel

typedef unsigned long long ull;

// ---------------- device scratch (no allocations allowed) ----------------
__device__ float  g_col [ (size_t)BB * CK * HW ];   // 226.5 MB deform-col
__device__ ull    g_wtp [ CK * 14 ];                // offset|mask weights, opair-packed
__device__ float4 g_wts [ (size_t)BB * KKc * HW ];  // separable bilinear weights
__device__ int    g_idxn[ (size_t)BB * KKc * HW ];  // gather base index
__device__ float  g_conv[ (size_t)BB * C * HW ];    // deform-conv output
__device__ float  g_act [ (size_t)BB * C * HW ];    // post BN+leakyrelu
__device__ float  g_sums[ 2 * C ];                  // atomic sum | sumsq

// packed f32x2 FMA (FFMA2)
#define FMA2(d, a, b) \
    asm("fma.rn.f32x2 %0, %1, %2, %0;" : "+l"(d) : "l"(a), "l"(b))

__device__ __forceinline__ ull bcast2(float v) {
    ull r; unsigned u = __float_as_uint(v);
    asm("mov.b64 %0, {%1, %1};" : "=l"(r) : "r"(u));
    return r;
}

// ---------------- weight prep (+ zero BN sums, folded) ----------------
__global__ void wprep_kernel(const float* __restrict__ offw,
                             const float* __restrict__ modw,
                             ull* __restrict__ wtp,
                             float* __restrict__ sums) {
    int t = blockIdx.x * blockDim.x + threadIdx.x;
    if (blockIdx.x == 0 && threadIdx.x < 2 * C) sums[threadIdx.x] = 0.f;
    if (t >= CK * 14) return;
    int ck = t / 14, j = t - ck * 14;
    int o0 = 2 * j, o1 = 2 * j + 1;
    float a = (o0 < 18) ? offw[o0 * CK + ck] : modw[(o0 - 18) * CK + ck];
    float b = 0.f;
    if (o1 < 27)
        b = (o1 < 18) ? offw[o1 * CK + ck] : modw[(o1 - 18) * CK + ck];
    float2 p = make_float2(a, b);
    wtp[t] = *reinterpret_cast<ull*>(&p);
}

// ---------------------------------------------------------------------------
// Direct 3x3 conv producing 27 outputs/pixel + separable bilinear tables.
// 512 threads = 8 channel-groups (12 ch each) x 64 pixel-columns x 2 rows.
// ---------------------------------------------------------------------------
#define OFF_SMEM (7 * 64 * 28 * 8)   // 100352 B

__global__ void __launch_bounds__(512) offconv_kernel(
    const ull* __restrict__ wtp, const float* __restrict__ X,
    const float* __restrict__ off_b, const float* __restrict__ mod_b,
    float4* __restrict__ wts, int* __restrict__ idxn)
{
    extern __shared__ ull red[];     // [7][64][28]

    int tid  = threadIdx.x;
    int lane = tid & 63;
    int grp  = tid >> 6;             // 0..7
    int half = blockIdx.x & 1;
    int h0   = (blockIdx.x >> 1) * 2;
    int b    = blockIdx.y;
    int pix  = half * 64 + lane;

    const float* Xb = X + (size_t)b * C * HW;

    ull acc[2][14];
    #pragma unroll
    for (int r = 0; r < 2; r++)
        #pragma unroll
        for (int j = 0; j < 14; j++) acc[r][j] = 0ull;

    bool xm_ok = (pix > 0), xp_ok = (pix < W - 1);
    int c0 = grp * 12;
    for (int ci = 0; ci < 12; ci++) {
        int c = c0 + ci;
        ull tb[4][3];
        #pragma unroll
        for (int rr = 0; rr < 4; rr++) {
            int y = h0 - 1 + rr;
            bool yok = (y >= 0) && (y < H);
            const float* row = Xb + (size_t)c * HW + y * W + pix;
            tb[rr][0] = bcast2((yok && xm_ok) ? row[-1] : 0.f);
            tb[rr][1] = bcast2(yok ? row[0] : 0.f);
            tb[rr][2] = bcast2((yok && xp_ok) ? row[1] : 0.f);
        }
        const ulonglong2* wrow =
            reinterpret_cast<const ulonglong2*>(wtp + (size_t)c * 9 * 14);
        #pragma unroll
        for (int ky = 0; ky < 3; ky++)
            #pragma unroll
            for (int kx = 0; kx < 3; kx++) {
                int tap = ky * 3 + kx;
                ull t0 = tb[ky][kx], t1 = tb[ky + 1][kx];
                #pragma unroll
                for (int j2 = 0; j2 < 7; j2++) {
                    ulonglong2 wv = wrow[tap * 7 + j2];
                    FMA2(acc[0][2 * j2],     wv.x, t0);
                    FMA2(acc[1][2 * j2],     wv.x, t1);
                    FMA2(acc[0][2 * j2 + 1], wv.y, t0);
                    FMA2(acc[1][2 * j2 + 1], wv.y, t1);
                }
            }
    }

    if (grp > 0) {
        ull* dst = red + ((size_t)(grp - 1) * 64 + lane) * 28;
        #pragma unroll
        for (int r = 0; r < 2; r++)
            #pragma unroll
            for (int j = 0; j < 14; j++)
                dst[r * 14 + j] = acc[r][j];
    }
    __syncthreads();
    if (grp != 0) return;

    #pragma unroll
    for (int g = 0; g < 7; g++) {
        const ull* src = red + ((size_t)g * 64 + lane) * 28;
        #pragma unroll
        for (int r = 0; r < 2; r++)
            #pragma unroll
            for (int j = 0; j < 14; j++) {
                ull p = src[r * 14 + j];
                float2 pa = *reinterpret_cast<float2*>(&acc[r][j]);
                float2 pb = *reinterpret_cast<float2*>(&p);
                pa.x += pb.x; pa.y += pb.y;
                acc[r][j] = *reinterpret_cast<ull*>(&pa);
            }
    }

    #pragma unroll
    for (int r = 0; r < 2; r++) {
        int h = h0 + r;
        #pragma unroll
        for (int kk = 0; kk < KKc; kk++) {
            float2 oyx = *reinterpret_cast<float2*>(&acc[r][kk]);
            float2 mp  = *reinterpret_cast<float2*>(&acc[r][9 + (kk >> 1)]);
            float mraw = (kk & 1) ? mp.y : mp.x;
            float offy = oyx.x + off_b[2 * kk];
            float offx = oyx.y + off_b[2 * kk + 1];
            float mval = 2.f / (1.f + expf(-(mraw + mod_b[kk])));

            float py = (float)h   - 1.f + (float)(kk / 3) + offy;
            float px = (float)pix - 1.f + (float)(kk % 3) + offx;
            float y0f = floorf(py), x0f = floorf(px);
            float dy = py - y0f, dx = px - x0f;
            int y0 = (int)y0f, x0 = (int)x0f;
            int y1 = y0 + 1,   x1 = x0 + 1;

            bool vx0 = (x0 >= 0) && (x0 < W);
            bool vx1 = (x1 >= 0) && (x1 < W);
            int x0c = min(max(x0, 0), W - 1), x1c = min(max(x1, 0), W - 1);
            int bx  = min(max(x0, 0), W - 2);
            float wxl = ((bx == x0c && vx0) ? (1.f - dx) : 0.f)
                      + ((bx == x1c && vx1) ? dx : 0.f);
            float wxr = ((bx + 1 == x0c && vx0) ? (1.f - dx) : 0.f)
                      + ((bx + 1 == x1c && vx1) ? dx : 0.f);

            bool vy0 = (y0 >= 0) && (y0 < H);
            bool vy1 = (y1 >= 0) && (y1 < H);
            int y0c = min(max(y0, 0), H - 1), y1c = min(max(y1, 0), H - 1);
            int by  = min(max(y0, 0), H - 2);
            float wyt = (((by == y0c && vy0) ? (1.f - dy) : 0.f)
                       + ((by == y1c && vy1) ? dy : 0.f)) * mval;
            float wyb = (((by + 1 == y0c && vy0) ? (1.f - dy) : 0.f)
                       + ((by + 1 == y1c && vy1) ? dy : 0.f)) * mval;

            size_t t = (((size_t)b * KKc + kk) << 14) + h * W + pix;
            wts[t]  = make_float4(wxl, wxr, wyt, wyb);
            idxn[t] = by * W + bx;
        }
    }
}

// ---------------- deformable im2col via precomputed tables ----------------
__global__ void deform_col_kernel(const float* __restrict__ in,
                                  const float4* __restrict__ wts,
                                  const int* __restrict__ idxn,
                                  float* __restrict__ col) {
    int t = blockIdx.x * blockDim.x + threadIdx.x;
    if (t >= BB * KKc * HW) return;
    int hw = t & (HW - 1);
    int u  = t >> 14;
    int kk = u % KKc;
    int b  = u / KKc;

    float4 w = wts[t];
    int base = idxn[t];

    const float* p = in + (size_t)b * C * HW;
    float* o = col + ((size_t)b * CK + kk) * HW + hw;
    #pragma unroll 4
    for (int c = 0; c < C; c++) {
        float top = p[base] * w.x + p[base + 1] * w.y;
        float bot = p[base + W] * w.x + p[base + W + 1] * w.y;
        *o = top * w.z + bot * w.w;
        p += HW;
        o += (size_t)KKc * HW;
    }
}

// ---------------- main GEMM (R11 proven) + fused BN-stats epilogue ----------
__global__ void __launch_bounds__(256, 2) sgemm96_kernel(
    const float* __restrict__ A,      // [96][864]
    const float* __restrict__ Bmat,   // [B][864][HW]
    float* __restrict__ Out,          // [B][96][HW]
    float* __restrict__ sums)         // [2][96] atomic accumulators
{
    constexpr int BK = 32, BN = 128, BM = 96;
    constexpr int NCHUNK = CK / BK;    // 27
    __shared__ float As[BK][BM + 2];   // row = 98 floats
    __shared__ float Bs[BK][BN];

    int tid = threadIdx.x;
    int b   = blockIdx.y;
    int n0  = blockIdx.x * BN;
    int tx  = tid & 15;
    int ty  = tid >> 4;

    const float* Bb = Bmat + (size_t)b * CK * HW;

    ull acc2[6][4];
    #pragma unroll
    for (int i = 0; i < 6; i++)
        #pragma unroll
        for (int j = 0; j < 4; j++) acc2[i][j] = 0ull;

    int br = tid >> 3;           // 0..31  (B row)
    int bq = tid & 7;            // 0..7   (col group)

    float4 ra[3], rb[4];

    auto gload = [&](int k0) {
        #pragma unroll
        for (int i = 0; i < 3; i++) {
            int e = tid + i * 256;
            int m = e >> 3, kq = e & 7;
            ra[i] = *reinterpret_cast<const float4*>(&A[m * CK + k0 + kq * 4]);
        }
        #pragma unroll
        for (int j = 0; j < 4; j++)
            rb[j] = *reinterpret_cast<const float4*>(
                Bb + (size_t)(k0 + br) * HW + n0 + bq * 4 + j * 32);
    };
    auto sstore = [&]() {
        #pragma unroll
        for (int i = 0; i < 3; i++) {
            int e = tid + i * 256;
            int m = e >> 3, kq = e & 7;
            As[kq * 4 + 0][m] = ra[i].x;
            As[kq * 4 + 1][m] = ra[i].y;
            As[kq * 4 + 2][m] = ra[i].z;
            As[kq * 4 + 3][m] = ra[i].w;
        }
        #pragma unroll
        for (int j = 0; j < 4; j++)
            *reinterpret_cast<float4*>(&Bs[br][bq * 4 + j * 32]) = rb[j];
    };

    gload(0);
    sstore();
    __syncthreads();

    for (int ch = 0; ch < NCHUNK; ch++) {
        if (ch + 1 < NCHUNK) gload((ch + 1) * BK);   // prefetch overlaps compute

        #pragma unroll
        for (int k = 0; k < BK; k++) {
            float2 a01 = *reinterpret_cast<const float2*>(&As[k][ty * 6]);
            float2 a23 = *reinterpret_cast<const float2*>(&As[k][ty * 6 + 2]);
            float2 a45 = *reinterpret_cast<const float2*>(&As[k][ty * 6 + 4]);
            ull a2[6];
            a2[0] = bcast2(a01.x); a2[1] = bcast2(a01.y);
            a2[2] = bcast2(a23.x); a2[3] = bcast2(a23.y);
            a2[4] = bcast2(a45.x); a2[5] = bcast2(a45.y);

            float4 bl = *reinterpret_cast<const float4*>(&Bs[k][tx * 4]);
            float4 bh = *reinterpret_cast<const float4*>(&Bs[k][64 + tx * 4]);
            float2 q0 = make_float2(bl.x, bl.y);
            float2 q1 = make_float2(bl.z, bl.w);
            float2 q2 = make_float2(bh.x, bh.y);
            float2 q3 = make_float2(bh.z, bh.w);
            ull b0 = *reinterpret_cast<ull*>(&q0);
            ull b1 = *reinterpret_cast<ull*>(&q1);
            ull b2v = *reinterpret_cast<ull*>(&q2);
            ull b3 = *reinterpret_cast<ull*>(&q3);

            #pragma unroll
            for (int i = 0; i < 6; i++) {
                FMA2(acc2[i][0], a2[i], b0);
                FMA2(acc2[i][1], a2[i], b1);
                FMA2(acc2[i][2], a2[i], b2v);
                FMA2(acc2[i][3], a2[i], b3);
            }
        }
        __syncthreads();
        if (ch + 1 < NCHUNK) {
            sstore();
            __syncthreads();
        }
    }

    #pragma unroll
    for (int i = 0; i < 6; i++) {
        int m = ty * 6 + i;
        float* op = Out + ((size_t)b * BM + m) * HW + n0 + tx * 4;
        float2 p0 = *reinterpret_cast<float2*>(&acc2[i][0]);
        float2 p1 = *reinterpret_cast<float2*>(&acc2[i][1]);
        float2 p2 = *reinterpret_cast<float2*>(&acc2[i][2]);
        float2 p3 = *reinterpret_cast<float2*>(&acc2[i][3]);
        *reinterpret_cast<float4*>(op)      = make_float4(p0.x, p0.y, p1.x, p1.y);
        *reinterpret_cast<float4*>(op + 64) = make_float4(p2.x, p2.y, p3.x, p3.y);

        float s = p0.x + p0.y + p1.x + p1.y + p2.x + p2.y + p3.x + p3.y;
        float q = p0.x * p0.x + p0.y * p0.y + p1.x * p1.x + p1.y * p1.y
                + p2.x * p2.x + p2.y * p2.y + p3.x * p3.x + p3.y * p3.y;
        #pragma unroll
        for (int off = 8; off > 0; off >>= 1) {
            s += __shfl_down_sync(0xffffffffu, s, off, 16);
            q += __shfl_down_sync(0xffffffffu, q, off, 16);
        }
        if (tx == 0) {
            atomicAdd(&sums[m], s);
            atomicAdd(&sums[C + m], q);
        }
    }
}

// ---------------- batch norm apply (stats finalized in-block) --------------
__global__ void bn_lrelu_kernel(const float* __restrict__ X,
                                const float* __restrict__ gam,
                                const float* __restrict__ bet,
                                const float* __restrict__ sums,
                                float* __restrict__ O) {
    __shared__ float sc, sh;
    int idx = blockIdx.x * blockDim.x + threadIdx.x;
    int c = (idx / HW) % C;          // constant per block (256 | HW)
    if (threadIdx.x == 0) {
        float inv = 1.f / (float)NPIX;
        float mean = sums[c] * inv;
        float var  = sums[C + c] * inv - mean * mean;
        float rstd = rsqrtf(var + 1e-5f);
        sc = rstd * gam[c];
        sh = bet[c] - mean * rstd * gam[c];
    }
    __syncthreads();
    float v = X[idx] * sc + sh;
    O[idx] = v >= 0.f ? v : 0.1f * v;
}

__global__ void bn_add_kernel(const float* __restrict__ Xres,
                              const float* __restrict__ Hc,
                              const float* __restrict__ gam,
                              const float* __restrict__ bet,
                              const float* __restrict__ sums,
                              float* __restrict__ O) {
    __shared__ float sc, sh;
    int idx = blockIdx.x * blockDim.x + threadIdx.x;
    int c = (idx / HW) % C;
    if (threadIdx.x == 0) {
        float inv = 1.f / (float)NPIX;
        float mean = sums[c] * inv;
        float var  = sums[C + c] * inv - mean * mean;
        float rstd = rsqrtf(var + 1e-5f);
        sc = rstd * gam[c];
        sh = bet[c] - mean * rstd * gam[c];
    }
    __syncthreads();
    O[idx] = Xres[idx] + Hc[idx] * sc + sh;
}

// ---------------- launch ----------------
extern "C" void kernel_launch(void* const* d_in, const int* in_sizes, int n_in,
                              void* d_out, int out_size) {
    const float* x        = (const float*)d_in[0];
    const float* d1_off_w = (const float*)d_in[1];
    const float* d1_off_b = (const float*)d_in[2];
    const float* d1_mod_w = (const float*)d_in[3];
    const float* d1_mod_b = (const float*)d_in[4];
    const float* d1_w     = (const float*)d_in[5];
    const float* d2_off_w = (const float*)d_in[6];
    const float* d2_off_b = (const float*)d_in[7];
    const float* d2_mod_w = (const float*)d_in[8];
    const float* d2_mod_b = (const float*)d_in[9];
    const float* d2_w     = (const float*)d_in[10];
    const float* bn_g     = (const float*)d_in[11];
    const float* bn_b     = (const float*)d_in[12];
    float* out = (float*)d_out;

    float *p_col, *p_conv, *p_act, *p_sums;
    ull* p_wtp; float4* p_wts; int* p_idxn;
    cudaGetSymbolAddress((void**)&p_col,   g_col);
    cudaGetSymbolAddress((void**)&p_wtp,   g_wtp);
    cudaGetSymbolAddress((void**)&p_wts,   g_wts);
    cudaGetSymbolAddress((void**)&p_idxn,  g_idxn);
    cudaGetSymbolAddress((void**)&p_conv,  g_conv);
    cudaGetSymbolAddress((void**)&p_act,   g_act);
    cudaGetSymbolAddress((void**)&p_sums,  g_sums);

    cudaFuncSetAttribute(offconv_kernel,
                         cudaFuncAttributeMaxDynamicSharedMemorySize, OFF_SMEM);

    const int NT = 256;
    const int nCol  = BB * KKc * HW;                 // 589824
    const int nElem = BB * C * HW;                   // 6291456
    dim3 gemm_grid(HW / 128, BB);                    // (128, 4)
    dim3 off_grid(H, BB);                            // (128, 4)

    // ---------- layer 1 ----------
    wprep_kernel<<<(CK * 14 + NT - 1) / NT, NT>>>(d1_off_w, d1_mod_w, p_wtp, p_sums);
    offconv_kernel<<<off_grid, 512, OFF_SMEM>>>(p_wtp, x, d1_off_b, d1_mod_b, p_wts, p_idxn);
    deform_col_kernel<<<(nCol + NT - 1) / NT, NT>>>(x, p_wts, p_idxn, p_col);
    sgemm96_kernel<<<gemm_grid, NT>>>(d1_w, p_col, p_conv, p_sums);
    bn_lrelu_kernel<<<nElem / NT, NT>>>(p_conv, bn_g, bn_b, p_sums, p_act);

    // ---------- layer 2 ----------
    wprep_kernel<<<(CK * 14 + NT - 1) / NT, NT>>>(d2_off_w, d2_mod_w, p_wtp, p_sums);
    offconv_kernel<<<off_grid, 512, OFF_SMEM>>>(p_wtp, p_act, d2_off_b, d2_mod_b, p_wts, p_idxn);
    deform_col_kernel<<<(nCol + NT - 1) / NT, NT>>>(p_act, p_wts, p_idxn, p_col);
    sgemm96_kernel<<<gemm_grid, NT>>>(d2_w, p_col, p_conv, p_sums);
    bn_add_kernel<<<nElem / NT, NT>>>(x, p_conv, bn_g, bn_b, p_sums, out);
}

// round 15
// speedup vs baseline: 1.0576x; 1.0369x over previous
#include <cuda_runtime.h>
#include <math.h>
#include <stdint.h>

#define BB 4
#define C 96
#define H 128
#define W 128
#define HW (H*W)          // 16384
#define KKc 9
#define CK (C*KKc)        // 864
#define NPIX (BB*HW)      // 65536 per channel

typedef unsigned long long ull;

// ---------------- device scratch (no allocations allowed) ----------------
__device__ float  g_col [ (size_t)BB * CK * HW ];   // 226.5 MB deform-col
__device__ ull    g_wtp [ CK * 14 ];                // offset|mask weights, opair-packed
__device__ float4 g_wts [ (size_t)BB * KKc * HW ];  // separable bilinear weights
__device__ int    g_idxn[ (size_t)BB * KKc * HW ];  // gather base index
__device__ float  g_conv[ (size_t)BB * C * HW ];    // deform-conv output
__device__ float  g_act [ (size_t)BB * C * HW ];    // post BN+leakyrelu
__device__ float  g_sums[ 2 * C ];                  // atomic sum | sumsq

// packed f32x2 FMA (FFMA2)
#define FMA2(d, a, b) \
    asm("fma.rn.f32x2 %0, %1, %2, %0;" : "+l"(d) : "l"(a), "l"(b))

__device__ __forceinline__ ull bcast2(float v) {
    ull r; unsigned u = __float_as_uint(v);
    asm("mov.b64 %0, {%1, %1};" : "=l"(r) : "r"(u));
    return r;
}

// ---------------- weight prep (+ zero BN sums, folded) ----------------
__global__ void wprep_kernel(const float* __restrict__ offw,
                             const float* __restrict__ modw,
                             ull* __restrict__ wtp,
                             float* __restrict__ sums) {
    int t = blockIdx.x * blockDim.x + threadIdx.x;
    if (blockIdx.x == 0 && threadIdx.x < 2 * C) sums[threadIdx.x] = 0.f;
    if (t >= CK * 14) return;
    int ck = t / 14, j = t - ck * 14;
    int o0 = 2 * j, o1 = 2 * j + 1;
    float a = (o0 < 18) ? offw[o0 * CK + ck] : modw[(o0 - 18) * CK + ck];
    float b = 0.f;
    if (o1 < 27)
        b = (o1 < 18) ? offw[o1 * CK + ck] : modw[(o1 - 18) * CK + ck];
    float2 p = make_float2(a, b);
    wtp[t] = *reinterpret_cast<ull*>(&p);
}

// ---------------------------------------------------------------------------
// Direct 3x3 conv producing 27 outputs/pixel + separable bilinear tables.
// 512 threads = 8 channel-groups (12 ch each) x 64 pixel-columns x 2 rows.
// ---------------------------------------------------------------------------
#define OFF_SMEM (7 * 64 * 28 * 8)   // 100352 B

__global__ void __launch_bounds__(512) offconv_kernel(
    const ull* __restrict__ wtp, const float* __restrict__ X,
    const float* __restrict__ off_b, const float* __restrict__ mod_b,
    float4* __restrict__ wts, int* __restrict__ idxn)
{
    extern __shared__ ull red[];     // [7][64][28]

    int tid  = threadIdx.x;
    int lane = tid & 63;
    int grp  = tid >> 6;             // 0..7
    int half = blockIdx.x & 1;
    int h0   = (blockIdx.x >> 1) * 2;
    int b    = blockIdx.y;
    int pix  = half * 64 + lane;

    const float* Xb = X + (size_t)b * C * HW;

    ull acc[2][14];
    #pragma unroll
    for (int r = 0; r < 2; r++)
        #pragma unroll
        for (int j = 0; j < 14; j++) acc[r][j] = 0ull;

    bool xm_ok = (pix > 0), xp_ok = (pix < W - 1);
    int c0 = grp * 12;
    for (int ci = 0; ci < 12; ci++) {
        int c = c0 + ci;
        ull tb[4][3];
        #pragma unroll
        for (int rr = 0; rr < 4; rr++) {
            int y = h0 - 1 + rr;
            bool yok = (y >= 0) && (y < H);
            const float* row = Xb + (size_t)c * HW + y * W + pix;
            tb[rr][0] = bcast2((yok && xm_ok) ? row[-1] : 0.f);
            tb[rr][1] = bcast2(yok ? row[0] : 0.f);
            tb[rr][2] = bcast2((yok && xp_ok) ? row[1] : 0.f);
        }
        const ulonglong2* wrow =
            reinterpret_cast<const ulonglong2*>(wtp + (size_t)c * 9 * 14);
        #pragma unroll
        for (int ky = 0; ky < 3; ky++)
            #pragma unroll
            for (int kx = 0; kx < 3; kx++) {
                int tap = ky * 3 + kx;
                ull t0 = tb[ky][kx], t1 = tb[ky + 1][kx];
                #pragma unroll
                for (int j2 = 0; j2 < 7; j2++) {
                    ulonglong2 wv = wrow[tap * 7 + j2];
                    FMA2(acc[0][2 * j2],     wv.x, t0);
                    FMA2(acc[1][2 * j2],     wv.x, t1);
                    FMA2(acc[0][2 * j2 + 1], wv.y, t0);
                    FMA2(acc[1][2 * j2 + 1], wv.y, t1);
                }
            }
    }

    if (grp > 0) {
        ull* dst = red + ((size_t)(grp - 1) * 64 + lane) * 28;
        #pragma unroll
        for (int r = 0; r < 2; r++)
            #pragma unroll
            for (int j = 0; j < 14; j++)
                dst[r * 14 + j] = acc[r][j];
    }
    __syncthreads();
    if (grp != 0) return;

    #pragma unroll
    for (int g = 0; g < 7; g++) {
        const ull* src = red + ((size_t)g * 64 + lane) * 28;
        #pragma unroll
        for (int r = 0; r < 2; r++)
            #pragma unroll
            for (int j = 0; j < 14; j++) {
                ull p = src[r * 14 + j];
                float2 pa = *reinterpret_cast<float2*>(&acc[r][j]);
                float2 pb = *reinterpret_cast<float2*>(&p);
                pa.x += pb.x; pa.y += pb.y;
                acc[r][j] = *reinterpret_cast<ull*>(&pa);
            }
    }

    #pragma unroll
    for (int r = 0; r < 2; r++) {
        int h = h0 + r;
        #pragma unroll
        for (int kk = 0; kk < KKc; kk++) {
            float2 oyx = *reinterpret_cast<float2*>(&acc[r][kk]);
            float2 mp  = *reinterpret_cast<float2*>(&acc[r][9 + (kk >> 1)]);
            float mraw = (kk & 1) ? mp.y : mp.x;
            float offy = oyx.x + off_b[2 * kk];
            float offx = oyx.y + off_b[2 * kk + 1];
            float mval = 2.f / (1.f + expf(-(mraw + mod_b[kk])));

            float py = (float)h   - 1.f + (float)(kk / 3) + offy;
            float px = (float)pix - 1.f + (float)(kk % 3) + offx;
            float y0f = floorf(py), x0f = floorf(px);
            float dy = py - y0f, dx = px - x0f;
            int y0 = (int)y0f, x0 = (int)x0f;
            int y1 = y0 + 1,   x1 = x0 + 1;

            bool vx0 = (x0 >= 0) && (x0 < W);
            bool vx1 = (x1 >= 0) && (x1 < W);
            int x0c = min(max(x0, 0), W - 1), x1c = min(max(x1, 0), W - 1);
            int bx  = min(max(x0, 0), W - 2);
            float wxl = ((bx == x0c && vx0) ? (1.f - dx) : 0.f)
                      + ((bx == x1c && vx1) ? dx : 0.f);
            float wxr = ((bx + 1 == x0c && vx0) ? (1.f - dx) : 0.f)
                      + ((bx + 1 == x1c && vx1) ? dx : 0.f);

            bool vy0 = (y0 >= 0) && (y0 < H);
            bool vy1 = (y1 >= 0) && (y1 < H);
            int y0c = min(max(y0, 0), H - 1), y1c = min(max(y1, 0), H - 1);
            int by  = min(max(y0, 0), H - 2);
            float wyt = (((by == y0c && vy0) ? (1.f - dy) : 0.f)
                       + ((by == y1c && vy1) ? dy : 0.f)) * mval;
            float wyb = (((by + 1 == y0c && vy0) ? (1.f - dy) : 0.f)
                       + ((by + 1 == y1c && vy1) ? dy : 0.f)) * mval;

            size_t t = (((size_t)b * KKc + kk) << 14) + h * W + pix;
            wts[t]  = make_float4(wxl, wxr, wyt, wyb);
            idxn[t] = by * W + bx;
        }
    }
}

// ---------------- deformable im2col via precomputed tables ----------------
__global__ void deform_col_kernel(const float* __restrict__ in,
                                  const float4* __restrict__ wts,
                                  const int* __restrict__ idxn,
                                  float* __restrict__ col) {
    int t = blockIdx.x * blockDim.x + threadIdx.x;
    if (t >= BB * KKc * HW) return;
    int hw = t & (HW - 1);
    int u  = t >> 14;
    int kk = u % KKc;
    int b  = u / KKc;

    float4 w = wts[t];
    int base = idxn[t];

    const float* p = in + (size_t)b * C * HW;
    float* o = col + ((size_t)b * CK + kk) * HW + hw;
    #pragma unroll 4
    for (int c = 0; c < C; c++) {
        float top = p[base] * w.x + p[base + 1] * w.y;
        float bot = p[base + W] * w.x + p[base + W + 1] * w.y;
        *o = top * w.z + bot * w.w;
        p += HW;
        o += (size_t)KKc * HW;
    }
}

// ---------------- main GEMM: double-buffered, single sync/chunk ------------
// dyn smem: As0[32*98] As1[32*98] Bs0[32*128] Bs1[32*128] = 57856 B
#define GEMM_SMEM 57856

#define GLOAD(k0)                                                             \
    {                                                                         \
        _Pragma("unroll")                                                     \
        for (int i = 0; i < 3; i++) {                                         \
            int e = tid + i * 256;                                            \
            int m = e >> 3, kq = e & 7;                                       \
            ra[i] = *reinterpret_cast<const float4*>(&A[m * CK + (k0) + kq * 4]); \
        }                                                                     \
        _Pragma("unroll")                                                     \
        for (int j = 0; j < 4; j++)                                           \
            rb[j] = *reinterpret_cast<const float4*>(                         \
                Bb + (size_t)((k0) + br) * HW + n0 + bq * 4 + j * 32);        \
    }

#define SSTORE(Asb, Bsb)                                                      \
    {                                                                         \
        _Pragma("unroll")                                                     \
        for (int i = 0; i < 3; i++) {                                         \
            int e = tid + i * 256;                                            \
            int m = e >> 3, kq = e & 7;                                       \
            (Asb)[(kq * 4 + 0) * 98 + m] = ra[i].x;                           \
            (Asb)[(kq * 4 + 1) * 98 + m] = ra[i].y;                           \
            (Asb)[(kq * 4 + 2) * 98 + m] = ra[i].z;                           \
            (Asb)[(kq * 4 + 3) * 98 + m] = ra[i].w;                           \
        }                                                                     \
        _Pragma("unroll")                                                     \
        for (int j = 0; j < 4; j++)                                           \
            *reinterpret_cast<float4*>(&(Bsb)[br * 128 + bq * 4 + j * 32]) = rb[j]; \
    }

#define COMPUTE(Asb, Bsb)                                                     \
    {                                                                         \
        _Pragma("unroll")                                                     \
        for (int k = 0; k < 32; k++) {                                        \
            float2 a01 = *reinterpret_cast<const float2*>(&(Asb)[k * 98 + ty * 6]);     \
            float2 a23 = *reinterpret_cast<const float2*>(&(Asb)[k * 98 + ty * 6 + 2]); \
            float2 a45 = *reinterpret_cast<const float2*>(&(Asb)[k * 98 + ty * 6 + 4]); \
            ull a2[6];                                                        \
            a2[0] = bcast2(a01.x); a2[1] = bcast2(a01.y);                     \
            a2[2] = bcast2(a23.x); a2[3] = bcast2(a23.y);                     \
            a2[4] = bcast2(a45.x); a2[5] = bcast2(a45.y);                     \
            float4 bl = *reinterpret_cast<const float4*>(&(Bsb)[k * 128 + tx * 4]);     \
            float4 bh = *reinterpret_cast<const float4*>(&(Bsb)[k * 128 + 64 + tx * 4]);\
            float2 q0 = make_float2(bl.x, bl.y);                              \
            float2 q1 = make_float2(bl.z, bl.w);                              \
            float2 q2 = make_float2(bh.x, bh.y);                              \
            float2 q3 = make_float2(bh.z, bh.w);                              \
            ull b0 = *reinterpret_cast<ull*>(&q0);                            \
            ull b1 = *reinterpret_cast<ull*>(&q1);                            \
            ull b2v = *reinterpret_cast<ull*>(&q2);                           \
            ull b3 = *reinterpret_cast<ull*>(&q3);                            \
            _Pragma("unroll")                                                 \
            for (int i = 0; i < 6; i++) {                                     \
                FMA2(acc2[i][0], a2[i], b0);                                  \
                FMA2(acc2[i][1], a2[i], b1);                                  \
                FMA2(acc2[i][2], a2[i], b2v);                                 \
                FMA2(acc2[i][3], a2[i], b3);                                  \
            }                                                                 \
        }                                                                     \
    }

__global__ void __launch_bounds__(256, 2) sgemm96_kernel(
    const float* __restrict__ A,      // [96][864]
    const float* __restrict__ Bmat,   // [B][864][HW]
    float* __restrict__ Out,          // [B][96][HW]
    float* __restrict__ sums)         // [2][96] atomic accumulators
{
    constexpr int BN = 128, BM = 96;
    extern __shared__ __align__(16) float dsm[];
    float* As0 = dsm;                  // 32*98
    float* As1 = dsm + 3136;
    float* Bs0 = dsm + 6272;           // 32*128
    float* Bs1 = dsm + 10368;

    int tid = threadIdx.x;
    int b   = blockIdx.y;
    int n0  = blockIdx.x * BN;
    int tx  = tid & 15;
    int ty  = tid >> 4;

    const float* Bb = Bmat + (size_t)b * CK * HW;

    ull acc2[6][4];
    #pragma unroll
    for (int i = 0; i < 6; i++)
        #pragma unroll
        for (int j = 0; j < 4; j++) acc2[i][j] = 0ull;

    int br = tid >> 3;           // 0..31  (B row)
    int bq = tid & 7;            // 0..7   (col group)

    float4 ra[3], rb[4];

    GLOAD(0);
    SSTORE(As0, Bs0);
    __syncthreads();

    // 13 pairs cover chunks 0..25; tail computes chunk 26 from buf0.
    for (int ch = 0; ch < 26; ch += 2) {
        GLOAD((ch + 1) * 32);
        COMPUTE(As0, Bs0);             // chunk ch
        SSTORE(As1, Bs1);              // chunk ch+1
        __syncthreads();

        GLOAD((ch + 2) * 32);          // chunk ch+2 (max 26, valid)
        COMPUTE(As1, Bs1);             // chunk ch+1
        SSTORE(As0, Bs0);              // chunk ch+2
        __syncthreads();
    }
    COMPUTE(As0, Bs0);                 // chunk 26

    #pragma unroll
    for (int i = 0; i < 6; i++) {
        int m = ty * 6 + i;
        float* op = Out + ((size_t)b * BM + m) * HW + n0 + tx * 4;
        float2 p0 = *reinterpret_cast<float2*>(&acc2[i][0]);
        float2 p1 = *reinterpret_cast<float2*>(&acc2[i][1]);
        float2 p2 = *reinterpret_cast<float2*>(&acc2[i][2]);
        float2 p3 = *reinterpret_cast<float2*>(&acc2[i][3]);
        *reinterpret_cast<float4*>(op)      = make_float4(p0.x, p0.y, p1.x, p1.y);
        *reinterpret_cast<float4*>(op + 64) = make_float4(p2.x, p2.y, p3.x, p3.y);

        float s = p0.x + p0.y + p1.x + p1.y + p2.x + p2.y + p3.x + p3.y;
        float q = p0.x * p0.x + p0.y * p0.y + p1.x * p1.x + p1.y * p1.y
                + p2.x * p2.x + p2.y * p2.y + p3.x * p3.x + p3.y * p3.y;
        #pragma unroll
        for (int off = 8; off > 0; off >>= 1) {
            s += __shfl_down_sync(0xffffffffu, s, off, 16);
            q += __shfl_down_sync(0xffffffffu, q, off, 16);
        }
        if (tx == 0) {
            atomicAdd(&sums[m], s);
            atomicAdd(&sums[C + m], q);
        }
    }
}

// ---------------- batch norm apply (stats finalized in-block) --------------
__global__ void bn_lrelu_kernel(const float* __restrict__ X,
                                const float* __restrict__ gam,
                                const float* __restrict__ bet,
                                const float* __restrict__ sums,
                                float* __restrict__ O) {
    __shared__ float sc, sh;
    int idx = blockIdx.x * blockDim.x + threadIdx.x;
    int c = (idx / HW) % C;          // constant per block (256 | HW)
    if (threadIdx.x == 0) {
        float inv = 1.f / (float)NPIX;
        float mean = sums[c] * inv;
        float var  = sums[C + c] * inv - mean * mean;
        float rstd = rsqrtf(var + 1e-5f);
        sc = rstd * gam[c];
        sh = bet[c] - mean * rstd * gam[c];
    }
    __syncthreads();
    float v = X[idx] * sc + sh;
    O[idx] = v >= 0.f ? v : 0.1f * v;
}

__global__ void bn_add_kernel(const float* __restrict__ Xres,
                              const float* __restrict__ Hc,
                              const float* __restrict__ gam,
                              const float* __restrict__ bet,
                              const float* __restrict__ sums,
                              float* __restrict__ O) {
    __shared__ float sc, sh;
    int idx = blockIdx.x * blockDim.x + threadIdx.x;
    int c = (idx / HW) % C;
    if (threadIdx.x == 0) {
        float inv = 1.f / (float)NPIX;
        float mean = sums[c] * inv;
        float var  = sums[C + c] * inv - mean * mean;
        float rstd = rsqrtf(var + 1e-5f);
        sc = rstd * gam[c];
        sh = bet[c] - mean * rstd * gam[c];
    }
    __syncthreads();
    O[idx] = Xres[idx] + Hc[idx] * sc + sh;
}

// ---------------- launch ----------------
extern "C" void kernel_launch(void* const* d_in, const int* in_sizes, int n_in,
                              void* d_out, int out_size) {
    const float* x        = (const float*)d_in[0];
    const float* d1_off_w = (const float*)d_in[1];
    const float* d1_off_b = (const float*)d_in[2];
    const float* d1_mod_w = (const float*)d_in[3];
    const float* d1_mod_b = (const float*)d_in[4];
    const float* d1_w     = (const float*)d_in[5];
    const float* d2_off_w = (const float*)d_in[6];
    const float* d2_off_b = (const float*)d_in[7];
    const float* d2_mod_w = (const float*)d_in[8];
    const float* d2_mod_b = (const float*)d_in[9];
    const float* d2_w     = (const float*)d_in[10];
    const float* bn_g     = (const float*)d_in[11];
    const float* bn_b     = (const float*)d_in[12];
    float* out = (float*)d_out;

    float *p_col, *p_conv, *p_act, *p_sums;
    ull* p_wtp; float4* p_wts; int* p_idxn;
    cudaGetSymbolAddress((void**)&p_col,   g_col);
    cudaGetSymbolAddress((void**)&p_wtp,   g_wtp);
    cudaGetSymbolAddress((void**)&p_wts,   g_wts);
    cudaGetSymbolAddress((void**)&p_idxn,  g_idxn);
    cudaGetSymbolAddress((void**)&p_conv,  g_conv);
    cudaGetSymbolAddress((void**)&p_act,   g_act);
    cudaGetSymbolAddress((void**)&p_sums,  g_sums);

    cudaFuncSetAttribute(offconv_kernel,
                         cudaFuncAttributeMaxDynamicSharedMemorySize, OFF_SMEM);
    cudaFuncSetAttribute(sgemm96_kernel,
                         cudaFuncAttributeMaxDynamicSharedMemorySize, GEMM_SMEM);

    const int NT = 256;
    const int nCol  = BB * KKc * HW;                 // 589824
    const int nElem = BB * C * HW;                   // 6291456
    dim3 gemm_grid(HW / 128, BB);                    // (128, 4)
    dim3 off_grid(H, BB);                            // (128, 4)

    // ---------- layer 1 ----------
    wprep_kernel<<<(CK * 14 + NT - 1) / NT, NT>>>(d1_off_w, d1_mod_w, p_wtp, p_sums);
    offconv_kernel<<<off_grid, 512, OFF_SMEM>>>(p_wtp, x, d1_off_b, d1_mod_b, p_wts, p_idxn);
    deform_col_kernel<<<(nCol + NT - 1) / NT, NT>>>(x, p_wts, p_idxn, p_col);
    sgemm96_kernel<<<gemm_grid, NT, GEMM_SMEM>>>(d1_w, p_col, p_conv, p_sums);
    bn_lrelu_kernel<<<nElem / NT, NT>>>(p_conv, bn_g, bn_b, p_sums, p_act);

    // ---------- layer 2 ----------
    wprep_kernel<<<(CK * 14 + NT - 1) / NT, NT>>>(d2_off_w, d2_mod_w, p_wtp, p_sums);
    offconv_kernel<<<off_grid, 512, OFF_SMEM>>>(p_wtp, p_act, d2_off_b, d2_mod_b, p_wts, p_idxn);
    deform_col_kernel<<<(nCol + NT - 1) / NT, NT>>>(p_act, p_wts, p_idxn, p_col);
    sgemm96_kernel<<<gemm_grid, NT, GEMM_SMEM>>>(d2_w, p_col, p_conv, p_sums);
    bn_add_kernel<<<nElem / NT, NT>>>(x, p_conv, bn_g, bn_b, p_sums, out);
}